// round 2
// baseline (speedup 1.0000x reference)
#include <cuda_runtime.h>
#include <math.h>

#define N_NODES   50000
#define IN_FEAT   128
#define HIDDEN    256
#define N_CLASSES 40
#define MAX_E     320000
#define BN_EPS    1e-5f

// ---------------- scratch (device globals; no allocation) ----------------
__device__ float g_bufA[N_NODES * HIDDEN];   // xw buffer
__device__ float g_bufB[N_NODES * HIDDEN];   // aggregated / activations
__device__ float g_dinv[N_NODES];            // degree -> rsqrt(degree)
__device__ float g_enorm[MAX_E];             // per-edge norm
__device__ float g_sum[HIDDEN];
__device__ float g_sumsq[HIDDEN];
__device__ float g_scale[HIDDEN];
__device__ float g_shift[HIDDEN];
__device__ int   g_is64;

// ---------------- edge-index dtype probe ----------------
// If edge_index is int64 (little-endian, values < 50000), every odd int32
// word of the buffer is 0. If int32, odd words are random node ids.
__global__ void k_detect(const int* __restrict__ ei32) {
    __shared__ int nz;
    if (threadIdx.x == 0) nz = 0;
    __syncthreads();
    for (int i = threadIdx.x; i < 1024; i += blockDim.x)
        if (ei32[2 * i + 1] != 0) nz = 1;
    __syncthreads();
    if (threadIdx.x == 0) g_is64 = (nz == 0) ? 1 : 0;
}

__device__ __forceinline__ int eget(const void* ei, long pos) {
    if (g_is64) return (int)__ldg(((const long long*)ei) + pos);
    return __ldg(((const int*)ei) + pos);
}

// ---------------- graph norm ----------------
__global__ void k_deg_init(int n) {
    int i = blockIdx.x * blockDim.x + threadIdx.x;
    if (i < n) g_dinv[i] = 1.0f;   // self-loop
}
__global__ void k_deg_edges(const void* __restrict__ ei, int E) {
    int e = blockIdx.x * blockDim.x + threadIdx.x;
    if (e >= E) return;
    int d = eget(ei, (long)E + e);
    atomicAdd(&g_dinv[d], 1.0f);
}
__global__ void k_dinv(int n) {
    int i = blockIdx.x * blockDim.x + threadIdx.x;
    if (i < n) g_dinv[i] = rsqrtf(g_dinv[i]);  // deg >= 1 always
}
__global__ void k_enorm(const void* __restrict__ ei, int E) {
    int e = blockIdx.x * blockDim.x + threadIdx.x;
    if (e >= E) return;
    g_enorm[e] = g_dinv[eget(ei, e)] * g_dinv[eget(ei, (long)E + e)];
}

// ---------------- fp32 tiled SGEMM: C[M,N] = A[M,K] @ B[K,N] ----------------
#define BM 128
#define BN 64
#define BK 16
#define TM 8
#define TN 4

__global__ void __launch_bounds__(256) sgemm(const float* __restrict__ A,
                                             const float* __restrict__ B,
                                             float* __restrict__ C,
                                             int M, int K, int N) {
    __shared__ __align__(16) float As[BK][BM + 4];
    __shared__ __align__(16) float Bs[BK][BN];
    const int tid = threadIdx.x;
    const int tx = tid & 15;    // 0..15 (cols)
    const int ty = tid >> 4;    // 0..15 (rows)
    const int rowBase = blockIdx.x * BM;
    const int colBase = blockIdx.y * BN;

    float acc[TM][TN];
#pragma unroll
    for (int m = 0; m < TM; m++)
#pragma unroll
        for (int n = 0; n < TN; n++) acc[m][n] = 0.0f;

    for (int k0 = 0; k0 < K; k0 += BK) {
#pragma unroll
        for (int i = 0; i < (BM * BK) / 256; i++) {
            int li = tid + i * 256;
            int kk = li & (BK - 1);
            int r  = li >> 4;
            int gr = rowBase + r;
            As[kk][r] = (gr < M) ? A[(long)gr * K + k0 + kk] : 0.0f;
        }
#pragma unroll
        for (int i = 0; i < (BK * BN) / 256; i++) {
            int li = tid + i * 256;
            int c  = li & (BN - 1);
            int kk = li >> 6;
            int gc = colBase + c;
            Bs[kk][c] = (gc < N) ? B[(long)(k0 + kk) * N + gc] : 0.0f;
        }
        __syncthreads();
#pragma unroll
        for (int kk = 0; kk < BK; kk++) {
            float4 a0 = *(const float4*)&As[kk][ty * TM];
            float4 a1 = *(const float4*)&As[kk][ty * TM + 4];
            float4 b0 = *(const float4*)&Bs[kk][tx * TN];
            float a[TM] = {a0.x, a0.y, a0.z, a0.w, a1.x, a1.y, a1.z, a1.w};
            float b[TN] = {b0.x, b0.y, b0.z, b0.w};
#pragma unroll
            for (int m = 0; m < TM; m++)
#pragma unroll
                for (int n = 0; n < TN; n++)
                    acc[m][n] = fmaf(a[m], b[n], acc[m][n]);
        }
        __syncthreads();
    }
#pragma unroll
    for (int m = 0; m < TM; m++) {
        int gr = rowBase + ty * TM + m;
        if (gr >= M) continue;
#pragma unroll
        for (int n = 0; n < TN; n++) {
            int gc = colBase + tx * TN + n;
            if (gc < N) C[(long)gr * N + gc] = acc[m][n];
        }
    }
}

// ---------------- aggregation ----------------
// out[i,:] = dinv[i]^2 * xw[i,:] + bias  (self-loop term + bias)
__global__ void k_self_bias(float* __restrict__ out, const float* __restrict__ xw,
                            const float* __restrict__ bias, int n, int F) {
    int idx = blockIdx.x * blockDim.x + threadIdx.x;
    if (idx >= n * F) return;
    int r = idx / F;
    int c = idx - r * F;
    float dv = g_dinv[r];
    out[idx] = dv * dv * xw[idx] + bias[c];
}

// warp per edge: out[dst,:] += norm[e] * xw[src,:]
__global__ void k_scatter(float* __restrict__ out, const float* __restrict__ xw,
                          const void* __restrict__ ei, int E, int F) {
    int gw   = (blockIdx.x * blockDim.x + threadIdx.x) >> 5;
    int lane = threadIdx.x & 31;
    if (gw >= E) return;
    int s = eget(ei, gw);
    int d = eget(ei, (long)E + gw);
    float nm = g_enorm[gw];
    const float* xs = xw + (long)s * F;
    float* od = out + (long)d * F;
    for (int c = lane; c < F; c += 32)
        atomicAdd(&od[c], nm * xs[c]);
}

// ---------------- batchnorm (training stats) + relu ----------------
__global__ void k_zero_stats() {
    int c = threadIdx.x;
    g_sum[c] = 0.0f;
    g_sumsq[c] = 0.0f;
}
__global__ void k_bn_stats(const float* __restrict__ h, int n) {
    int c = threadIdx.x;  // blockDim.x == HIDDEN
    int chunk = (n + gridDim.x - 1) / gridDim.x;
    int r0 = blockIdx.x * chunk;
    int r1 = min(n, r0 + chunk);
    float s = 0.0f, ss = 0.0f;
    for (int r = r0; r < r1; r++) {
        float v = h[(long)r * HIDDEN + c];
        s += v;
        ss += v * v;
    }
    atomicAdd(&g_sum[c], s);
    atomicAdd(&g_sumsq[c], ss);
}
__global__ void k_bn_finalize(const float* __restrict__ gamma,
                              const float* __restrict__ beta, int n) {
    int c = threadIdx.x;
    float inv_n = 1.0f / (float)n;
    float mean = g_sum[c] * inv_n;
    float var  = g_sumsq[c] * inv_n - mean * mean;
    float sc = gamma[c] * rsqrtf(var + BN_EPS);
    g_scale[c] = sc;
    g_shift[c] = beta[c] - mean * sc;
}
__global__ void k_bn_relu(float* __restrict__ h, int total) {
    int i = blockIdx.x * blockDim.x + threadIdx.x;
    if (i >= total) return;
    int c = i & (HIDDEN - 1);
    h[i] = fmaxf(0.0f, fmaf(h[i], g_scale[c], g_shift[c]));
}

// ---------------- log_softmax over 40 classes (warp per row) ----------------
__global__ void k_logsoftmax(float* __restrict__ out, int n) {
    int gw   = (blockIdx.x * blockDim.x + threadIdx.x) >> 5;
    int lane = threadIdx.x & 31;
    if (gw >= n) return;
    float* row = out + (long)gw * N_CLASSES;
    float v0 = row[lane];  // lane < 32 < 40, always valid
    float v1 = (lane + 32 < N_CLASSES) ? row[lane + 32] : -1e30f;
    float m = fmaxf(v0, v1);
#pragma unroll
    for (int o = 16; o > 0; o >>= 1)
        m = fmaxf(m, __shfl_xor_sync(0xFFFFFFFFu, m, o));
    float s = expf(v0 - m) + ((lane + 32 < N_CLASSES) ? expf(v1 - m) : 0.0f);
#pragma unroll
    for (int o = 16; o > 0; o >>= 1)
        s += __shfl_xor_sync(0xFFFFFFFFu, s, o);
    float lse = m + logf(s);
    row[lane] = v0 - lse;
    if (lane + 32 < N_CLASSES) row[lane + 32] = v1 - lse;
}

// ---------------- launch ----------------
extern "C" void kernel_launch(void* const* d_in, const int* in_sizes, int n_in,
                              void* d_out, int out_size) {
    const float* x   = (const float*)d_in[0];
    const void*  ei  = d_in[1];
    const float* W1  = (const float*)d_in[2];
    const float* b1  = (const float*)d_in[3];
    const float* g1  = (const float*)d_in[4];
    const float* be1 = (const float*)d_in[5];
    const float* W2  = (const float*)d_in[6];
    const float* b2  = (const float*)d_in[7];
    const float* g2  = (const float*)d_in[8];
    const float* be2 = (const float*)d_in[9];
    const float* W3  = (const float*)d_in[10];
    const float* b3  = (const float*)d_in[11];
    float* out = (float*)d_out;

    const int N = N_NODES;
    const int E = in_sizes[1] / 2;

    float *pA, *pB;
    cudaGetSymbolAddress((void**)&pA, g_bufA);
    cudaGetSymbolAddress((void**)&pB, g_bufB);

    // graph normalization
    k_detect<<<1, 256>>>((const int*)ei);
    k_deg_init<<<(N + 255) / 256, 256>>>(N);
    k_deg_edges<<<(E + 255) / 256, 256>>>(ei, E);
    k_dinv<<<(N + 255) / 256, 256>>>(N);
    k_enorm<<<(E + 255) / 256, 256>>>(ei, E);

    dim3 gHid((N + BM - 1) / BM, (HIDDEN + BN - 1) / BN);
    dim3 gCls((N + BM - 1) / BM, (N_CLASSES + BN - 1) / BN);
    int totH = N * HIDDEN;
    int totC = N * N_CLASSES;
    int scatterBlocks = (E * 32 + 255) / 256;

    // ---- layer 1 ----
    sgemm<<<gHid, 256>>>(x, W1, pA, N, IN_FEAT, HIDDEN);
    k_self_bias<<<(totH + 255) / 256, 256>>>(pB, pA, b1, N, HIDDEN);
    k_scatter<<<scatterBlocks, 256>>>(pB, pA, ei, E, HIDDEN);
    k_zero_stats<<<1, HIDDEN>>>();
    k_bn_stats<<<512, HIDDEN>>>(pB, N);
    k_bn_finalize<<<1, HIDDEN>>>(g1, be1, N);
    k_bn_relu<<<(totH + 255) / 256, 256>>>(pB, totH);

    // ---- layer 2 ----
    sgemm<<<gHid, 256>>>(pB, W2, pA, N, HIDDEN, HIDDEN);
    k_self_bias<<<(totH + 255) / 256, 256>>>(pB, pA, b2, N, HIDDEN);
    k_scatter<<<scatterBlocks, 256>>>(pB, pA, ei, E, HIDDEN);
    k_zero_stats<<<1, HIDDEN>>>();
    k_bn_stats<<<512, HIDDEN>>>(pB, N);
    k_bn_finalize<<<1, HIDDEN>>>(g2, be2, N);
    k_bn_relu<<<(totH + 255) / 256, 256>>>(pB, totH);

    // ---- output layer ----
    sgemm<<<gCls, 256>>>(pB, W3, pA, N, HIDDEN, N_CLASSES);
    k_self_bias<<<(totC + 255) / 256, 256>>>(out, pA, b3, N, N_CLASSES);
    k_scatter<<<scatterBlocks, 256>>>(out, pA, ei, E, N_CLASSES);
    k_logsoftmax<<<(N * 32 + 255) / 256, 256>>>(out, N);
}

// round 4
// speedup vs baseline: 1.0499x; 1.0499x over previous
#include <cuda_runtime.h>
#include <cuda_bf16.h>
#include <math.h>
#include <stdint.h>

#define N_NODES   50000
#define IN_FEAT   128
#define HIDDEN    256
#define N_CLASSES 40
#define MAX_E     320000
#define BN_EPS    1e-5f

// ---------------- scratch (device globals; no allocation) ----------------
__device__ float g_bufA[N_NODES * HIDDEN];   // xw buffer
__device__ float g_bufB[N_NODES * HIDDEN];   // layer-1 aggregated
__device__ float g_bufC[N_NODES * HIDDEN];   // layer-2 aggregated
__device__ float g_dinv[N_NODES];
__device__ float g_enorm[MAX_E];
__device__ float g_sum[HIDDEN];
__device__ float g_sumsq[HIDDEN];
__device__ float g_scale[HIDDEN];
__device__ float g_shift[HIDDEN];
__device__ int   g_is64;

// ---------------- edge-index dtype probe ----------------
__global__ void k_detect(const int* __restrict__ ei32) {
    __shared__ int nz;
    if (threadIdx.x == 0) nz = 0;
    __syncthreads();
    for (int i = threadIdx.x; i < 1024; i += blockDim.x)
        if (ei32[2 * i + 1] != 0) nz = 1;
    __syncthreads();
    if (threadIdx.x == 0) g_is64 = (nz == 0) ? 1 : 0;
}
__device__ __forceinline__ int eget(const void* ei, long pos) {
    if (g_is64) return (int)__ldg(((const long long*)ei) + pos);
    return __ldg(((const int*)ei) + pos);
}

// ---------------- graph norm ----------------
__global__ void k_deg_init(int n) {
    int i = blockIdx.x * blockDim.x + threadIdx.x;
    if (i < n) g_dinv[i] = 1.0f;
}
__global__ void k_deg_edges(const void* __restrict__ ei, int E) {
    int e = blockIdx.x * blockDim.x + threadIdx.x;
    if (e >= E) return;
    atomicAdd(&g_dinv[eget(ei, (long)E + e)], 1.0f);
}
__global__ void k_dinv(int n) {
    int i = blockIdx.x * blockDim.x + threadIdx.x;
    if (i < n) g_dinv[i] = rsqrtf(g_dinv[i]);
}
__global__ void k_enorm(const void* __restrict__ ei, int E) {
    int e = blockIdx.x * blockDim.x + threadIdx.x;
    if (e >= E) return;
    g_enorm[e] = g_dinv[eget(ei, e)] * g_dinv[eget(ei, (long)E + e)];
}

// ---------------- HMMA helpers ----------------
__device__ __forceinline__ void ldm_x4(uint32_t* r, const void* p) {
    uint32_t a = (uint32_t)__cvta_generic_to_shared(p);
    asm volatile("ldmatrix.sync.aligned.m8n8.x4.shared.b16 {%0,%1,%2,%3}, [%4];"
                 : "=r"(r[0]), "=r"(r[1]), "=r"(r[2]), "=r"(r[3]) : "r"(a));
}
__device__ __forceinline__ void ldm_x4_t(uint32_t* r, const void* p) {
    uint32_t a = (uint32_t)__cvta_generic_to_shared(p);
    asm volatile("ldmatrix.sync.aligned.m8n8.x4.trans.shared.b16 {%0,%1,%2,%3}, [%4];"
                 : "=r"(r[0]), "=r"(r[1]), "=r"(r[2]), "=r"(r[3]) : "r"(a));
}
__device__ __forceinline__ void mma_bf16(float* c, const uint32_t* a, const uint32_t* b) {
    asm volatile(
        "mma.sync.aligned.m16n8k16.row.col.f32.bf16.bf16.f32 "
        "{%0,%1,%2,%3}, {%4,%5,%6,%7}, {%8,%9}, {%0,%1,%2,%3};"
        : "+f"(c[0]), "+f"(c[1]), "+f"(c[2]), "+f"(c[3])
        : "r"(a[0]), "r"(a[1]), "r"(a[2]), "r"(a[3]), "r"(b[0]), "r"(b[1]));
}
__device__ __forceinline__ void split_bf16(float v, unsigned short& h, unsigned short& l) {
    __nv_bfloat16 hb = __float2bfloat16(v);
    __nv_bfloat16 lb = __float2bfloat16(v - __bfloat162float(hb));
    h = __bfloat16_as_ushort(hb);
    l = __bfloat16_as_ushort(lb);
}

// ---------------- HMMA GEMM with fused BN/ReLU input + self-loop/bias epilogue ----
// C = act(A) @ W ; act(a)=relu(a*scale[k]+shift[k]) if scale else a
// xw = C ; oinit = dinv^2 * C + bias
// bf16 hi/lo 3-product split for fp32-grade accuracy.
template <int BN_T>
__global__ void __launch_bounds__(256) gemm_mma(
    const float* __restrict__ A, const float* __restrict__ W,
    const float* __restrict__ scale, const float* __restrict__ shift,
    const float* __restrict__ bias,
    float* __restrict__ xw, float* __restrict__ oinit,
    int M, int K, int Nr)
{
    constexpr int BM = 128, BK = 32;
    constexpr int ASTR = BK + 8;      // 40 bf16
    constexpr int BSTR = BN_T + 8;
    constexpr int BN_W = BN_T / 2;    // warp col span (warps: 4 in M x 2 in N)
    constexpr int NT = BN_W / 8;      // n8 tiles per warp
    constexpr int NG = BN_W / 16;     // x4-ldmatrix groups per warp

    __shared__ __nv_bfloat16 As[2][BM][ASTR];
    __shared__ __nv_bfloat16 Bs[2][BK][BSTR];

    const int tid = threadIdx.x;
    const int wid = tid >> 5, lane = tid & 31;
    const int warp_m = wid >> 1, warp_n = wid & 1;
    const int blockRow = blockIdx.x * BM;
    const int colBase = blockIdx.y * BN_T;

    float acc[2][NT][4];
#pragma unroll
    for (int m = 0; m < 2; m++)
#pragma unroll
        for (int n = 0; n < NT; n++)
#pragma unroll
            for (int j = 0; j < 4; j++) acc[m][n][j] = 0.0f;

    for (int k0 = 0; k0 < K; k0 += BK) {
        __syncthreads();
        // ---- load + convert A tile [BM][BK] ----
#pragma unroll
        for (int p = 0; p < 4; p++) {
            int row = (tid >> 3) + p * 32;
            int c4 = (tid & 7) * 4;
            long gr = blockRow + row;
            float v[4] = {0.f, 0.f, 0.f, 0.f};
            if (gr < M) {
                float4 t = *(const float4*)&A[gr * K + k0 + c4];
                v[0] = t.x; v[1] = t.y; v[2] = t.z; v[3] = t.w;
                if (scale) {
#pragma unroll
                    for (int j = 0; j < 4; j++) {
                        int k = k0 + c4 + j;
                        v[j] = fmaxf(0.0f, fmaf(v[j], __ldg(&scale[k]), __ldg(&shift[k])));
                    }
                }
            }
            unsigned short h[4], l[4];
#pragma unroll
            for (int j = 0; j < 4; j++) split_bf16(v[j], h[j], l[j]);
            *(ushort4*)&As[0][row][c4] = make_ushort4(h[0], h[1], h[2], h[3]);
            *(ushort4*)&As[1][row][c4] = make_ushort4(l[0], l[1], l[2], l[3]);
        }
        // ---- load + convert B tile [BK][BN_T] ----
#pragma unroll
        for (int p = 0; p < BN_T / 32; p++) {
            int row = tid >> 3;
            int colt = (tid & 7) * 4 + p * 32;
            int gcol = colBase + colt;
            float v[4] = {0.f, 0.f, 0.f, 0.f};
            if (gcol < Nr) {
                float4 t = *(const float4*)&W[(long)(k0 + row) * Nr + gcol];
                v[0] = t.x; v[1] = t.y; v[2] = t.z; v[3] = t.w;
            }
            unsigned short h[4], l[4];
#pragma unroll
            for (int j = 0; j < 4; j++) split_bf16(v[j], h[j], l[j]);
            *(ushort4*)&Bs[0][row][colt] = make_ushort4(h[0], h[1], h[2], h[3]);
            *(ushort4*)&Bs[1][row][colt] = make_ushort4(l[0], l[1], l[2], l[3]);
        }
        __syncthreads();

        // ---- compute: 2 k16 steps, 3 products each ----
#pragma unroll
        for (int ks = 0; ks < 2; ks++) {
            uint32_t ah[2][4], al[2][4];
#pragma unroll
            for (int tm = 0; tm < 2; tm++) {
                int r = warp_m * 32 + tm * 16 + (lane & 15);
                int cc = ks * 16 + (lane >> 4) * 8;
                ldm_x4(ah[tm], &As[0][r][cc]);
                ldm_x4(al[tm], &As[1][r][cc]);
            }
            uint32_t bh[NG][4], bl[NG][4];
#pragma unroll
            for (int ng = 0; ng < NG; ng++) {
                int r = ks * 16 + (lane & 15);
                int cc = warp_n * BN_W + ng * 16 + (lane >> 4) * 8;
                ldm_x4_t(bh[ng], &Bs[0][r][cc]);
                ldm_x4_t(bl[ng], &Bs[1][r][cc]);
            }
#pragma unroll
            for (int tm = 0; tm < 2; tm++)
#pragma unroll
                for (int nn = 0; nn < NT; nn++) {
                    const uint32_t* bH = &bh[nn >> 1][(nn & 1) * 2];
                    const uint32_t* bL = &bl[nn >> 1][(nn & 1) * 2];
                    mma_bf16(acc[tm][nn], ah[tm], bH);
                    mma_bf16(acc[tm][nn], ah[tm], bL);
                    mma_bf16(acc[tm][nn], al[tm], bH);
                }
        }
    }

    // ---- epilogue: xw = C, oinit = dinv^2*C + bias ----
    const int warpCol = colBase + warp_n * BN_W;
#pragma unroll
    for (int tm = 0; tm < 2; tm++) {
        int r0 = blockRow + warp_m * 32 + tm * 16 + (lane >> 2);
#pragma unroll
        for (int h = 0; h < 2; h++) {
            long row = r0 + h * 8;
            if (row >= M) continue;
            float dv = g_dinv[row];
            float dv2 = dv * dv;
#pragma unroll
            for (int nn = 0; nn < NT; nn++) {
                int col = warpCol + nn * 8 + (lane & 3) * 2;
                if (col >= Nr) continue;
                float2 v = make_float2(acc[tm][nn][h * 2], acc[tm][nn][h * 2 + 1]);
                *(float2*)&xw[row * Nr + col] = v;
                float2 o = make_float2(fmaf(dv2, v.x, __ldg(&bias[col])),
                                       fmaf(dv2, v.y, __ldg(&bias[col + 1])));
                *(float2*)&oinit[row * Nr + col] = o;
            }
        }
    }
}

// ---------------- edge scatter: out[dst,:] += norm[e] * xw[src,:] ----------------
__global__ void k_scatter(float* __restrict__ out, const float* __restrict__ xw,
                          const void* __restrict__ ei, int E, int F) {
    int gw   = (blockIdx.x * blockDim.x + threadIdx.x) >> 5;
    int lane = threadIdx.x & 31;
    if (gw >= E) return;
    int s = eget(ei, gw);
    int d = eget(ei, (long)E + gw);
    float nm = g_enorm[gw];
    const float4* xs = (const float4*)(xw + (long)s * F);
    float* od = out + (long)d * F;
    int F4 = F >> 2;
    for (int c = lane; c < F4; c += 32) {
        float4 v = __ldg(&xs[c]);
        atomicAdd(&od[c * 4 + 0], nm * v.x);
        atomicAdd(&od[c * 4 + 1], nm * v.y);
        atomicAdd(&od[c * 4 + 2], nm * v.z);
        atomicAdd(&od[c * 4 + 3], nm * v.w);
    }
}

// ---------------- batchnorm stats -> scale/shift ----------------
__global__ void k_zero_stats() {
    int c = threadIdx.x;
    g_sum[c] = 0.0f;
    g_sumsq[c] = 0.0f;
}
__global__ void k_bn_stats(const float* __restrict__ h, int n) {
    int c = threadIdx.x;
    int chunk = (n + gridDim.x - 1) / gridDim.x;
    int r0 = blockIdx.x * chunk;
    int r1 = min(n, r0 + chunk);
    float s = 0.0f, ss = 0.0f;
    for (int r = r0; r < r1; r++) {
        float v = h[(long)r * HIDDEN + c];
        s += v;
        ss += v * v;
    }
    atomicAdd(&g_sum[c], s);
    atomicAdd(&g_sumsq[c], ss);
}
__global__ void k_bn_finalize(const float* __restrict__ gamma,
                              const float* __restrict__ beta, int n) {
    int c = threadIdx.x;
    float inv_n = 1.0f / (float)n;
    float mean = g_sum[c] * inv_n;
    float var  = g_sumsq[c] * inv_n - mean * mean;
    float sc = gamma[c] * rsqrtf(var + BN_EPS);
    g_scale[c] = sc;
    g_shift[c] = beta[c] - mean * sc;
}

// ---------------- log_softmax (warp per row) ----------------
__global__ void k_logsoftmax(float* __restrict__ out, int n) {
    int gw   = (blockIdx.x * blockDim.x + threadIdx.x) >> 5;
    int lane = threadIdx.x & 31;
    if (gw >= n) return;
    float* row = out + (long)gw * N_CLASSES;
    float v0 = row[lane];
    float v1 = (lane + 32 < N_CLASSES) ? row[lane + 32] : -1e30f;
    float m = fmaxf(v0, v1);
#pragma unroll
    for (int o = 16; o > 0; o >>= 1)
        m = fmaxf(m, __shfl_xor_sync(0xFFFFFFFFu, m, o));
    float s = expf(v0 - m) + ((lane + 32 < N_CLASSES) ? expf(v1 - m) : 0.0f);
#pragma unroll
    for (int o = 16; o > 0; o >>= 1)
        s += __shfl_xor_sync(0xFFFFFFFFu, s, o);
    float lse = m + logf(s);
    row[lane] = v0 - lse;
    if (lane + 32 < N_CLASSES) row[lane + 32] = v1 - lse;
}

// ---------------- launch ----------------
extern "C" void kernel_launch(void* const* d_in, const int* in_sizes, int n_in,
                              void* d_out, int out_size) {
    const float* x   = (const float*)d_in[0];
    const void*  ei  = d_in[1];
    const float* W1  = (const float*)d_in[2];
    const float* b1  = (const float*)d_in[3];
    const float* g1  = (const float*)d_in[4];
    const float* be1 = (const float*)d_in[5];
    const float* W2  = (const float*)d_in[6];
    const float* b2  = (const float*)d_in[7];
    const float* g2  = (const float*)d_in[8];
    const float* be2 = (const float*)d_in[9];
    const float* W3  = (const float*)d_in[10];
    const float* b3  = (const float*)d_in[11];
    float* out = (float*)d_out;

    const int N = N_NODES;
    const int E = in_sizes[1] / 2;

    float *pA, *pB, *pC, *pScale, *pShift;
    cudaGetSymbolAddress((void**)&pA, g_bufA);
    cudaGetSymbolAddress((void**)&pB, g_bufB);
    cudaGetSymbolAddress((void**)&pC, g_bufC);
    cudaGetSymbolAddress((void**)&pScale, g_scale);
    cudaGetSymbolAddress((void**)&pShift, g_shift);

    // graph normalization
    k_detect<<<1, 256>>>((const int*)ei);
    k_deg_init<<<(N + 255) / 256, 256>>>(N);
    k_deg_edges<<<(E + 255) / 256, 256>>>(ei, E);
    k_dinv<<<(N + 255) / 256, 256>>>(N);
    k_enorm<<<(E + 255) / 256, 256>>>(ei, E);

    const int mTiles = (N + 127) / 128;
    dim3 gHid(mTiles, 2);   // 2 x BN_T=128 covers N=256
    dim3 gCls(mTiles, 1);   // BN_T=64 covers N=40 (padded)
    int scatterBlocks = (E * 32 + 255) / 256;

    // ---- layer 1: xw=pA, init/agg=pB ----
    gemm_mma<128><<<gHid, 256>>>(x, W1, nullptr, nullptr, b1, pA, pB,
                                 N, IN_FEAT, HIDDEN);
    k_scatter<<<scatterBlocks, 256>>>(pB, pA, ei, E, HIDDEN);
    k_zero_stats<<<1, HIDDEN>>>();
    k_bn_stats<<<512, HIDDEN>>>(pB, N);
    k_bn_finalize<<<1, HIDDEN>>>(g1, be1, N);

    // ---- layer 2: A=pB (BN+ReLU fused), xw=pA, init/agg=pC ----
    gemm_mma<128><<<gHid, 256>>>(pB, W2, pScale, pShift, b2, pA, pC,
                                 N, HIDDEN, HIDDEN);
    k_scatter<<<scatterBlocks, 256>>>(pC, pA, ei, E, HIDDEN);
    k_zero_stats<<<1, HIDDEN>>>();
    k_bn_stats<<<512, HIDDEN>>>(pC, N);
    k_bn_finalize<<<1, HIDDEN>>>(g2, be2, N);

    // ---- layer 3: A=pC (BN+ReLU fused), xw=pA (stride 40), init/agg=out ----
    gemm_mma<64><<<gCls, 256>>>(pC, W3, pScale, pShift, b3, pA, out,
                                N, HIDDEN, N_CLASSES);
    k_scatter<<<scatterBlocks, 256>>>(out, pA, ei, E, N_CLASSES);
    k_logsoftmax<<<(N * 32 + 255) / 256, 256>>>(out, N);
}

// round 5
// speedup vs baseline: 1.9792x; 1.8852x over previous
#include <cuda_runtime.h>
#include <cuda_bf16.h>
#include <math.h>
#include <stdint.h>

#define N_NODES   50000
#define IN_FEAT   128
#define HIDDEN    256
#define N_CLASSES 40
#define MAX_E     320000
#define BN_EPS    1e-5f

// ---------------- scratch (device globals; no allocation) ----------------
__device__ float g_bufA[N_NODES * HIDDEN];   // xw buffer
__device__ float g_bufB[N_NODES * HIDDEN];   // layer-1 aggregated
__device__ float g_bufC[N_NODES * HIDDEN];   // layer-2 aggregated
__device__ float g_dinv[N_NODES];
__device__ int   g_cnt[N_NODES];             // in-degree histogram
__device__ int   g_rowptr[N_NODES + 1];      // CSR row offsets (by dst)
__device__ int   g_cursor[N_NODES];          // fill cursors
__device__ int   g_esrc[MAX_E];              // src ids sorted by dst
__device__ float g_enrm[MAX_E];              // edge norms sorted by dst
__device__ float g_sum[HIDDEN];
__device__ float g_sumsq[HIDDEN];
__device__ float g_scale[HIDDEN];
__device__ float g_shift[HIDDEN];
__device__ int   g_is64;

// ---------------- dtype probe + zero histogram (one launch) ----------------
__global__ void k_detect_zero(const int* __restrict__ ei32, int n) {
    for (int i = threadIdx.x; i < n; i += blockDim.x) g_cnt[i] = 0;
    __shared__ int nz;
    if (threadIdx.x == 0) nz = 0;
    __syncthreads();
    for (int i = threadIdx.x; i < 1024; i += blockDim.x)
        if (ei32[2 * i + 1] != 0) nz = 1;
    __syncthreads();
    if (threadIdx.x == 0) g_is64 = (nz == 0) ? 1 : 0;
}
__device__ __forceinline__ int eget(const void* ei, long pos) {
    if (g_is64) return (int)__ldg(((const long long*)ei) + pos);
    return __ldg(((const int*)ei) + pos);
}

// ---------------- CSR build ----------------
__global__ void k_hist(const void* __restrict__ ei, int E) {
    int e = blockIdx.x * blockDim.x + threadIdx.x;
    if (e >= E) return;
    atomicAdd(&g_cnt[eget(ei, (long)E + e)], 1);
}
__global__ void k_dinv(int n) {
    int i = blockIdx.x * blockDim.x + threadIdx.x;
    if (i < n) g_dinv[i] = rsqrtf(1.0f + (float)g_cnt[i]);  // +1 self loop
}
// single-CTA hierarchical exclusive scan over g_cnt -> g_rowptr/g_cursor
__global__ void __launch_bounds__(1024) k_scan(int n) {
    __shared__ int wsum[32];
    __shared__ int carry;
    const int tid = threadIdx.x;
    const int lane = tid & 31, w = tid >> 5;
    if (tid == 0) carry = 0;
    __syncthreads();
    const int nch = (n + 1023) >> 10;
    for (int ch = 0; ch < nch; ch++) {
        int i = (ch << 10) + tid;
        int v = (i < n) ? g_cnt[i] : 0;
        int inc = v;
#pragma unroll
        for (int o = 1; o < 32; o <<= 1) {
            int t = __shfl_up_sync(0xFFFFFFFFu, inc, o);
            if (lane >= o) inc += t;
        }
        if (lane == 31) wsum[w] = inc;
        __syncthreads();
        if (w == 0) {
            int s = wsum[lane];
#pragma unroll
            for (int o = 1; o < 32; o <<= 1) {
                int t = __shfl_up_sync(0xFFFFFFFFu, s, o);
                if (lane >= o) s += t;
            }
            wsum[lane] = s;
        }
        __syncthreads();
        int woff = (w == 0) ? 0 : wsum[w - 1];
        int excl = carry + woff + inc - v;
        if (i < n) { g_rowptr[i] = excl; g_cursor[i] = excl; }
        __syncthreads();
        if (tid == 0) carry += wsum[31];
        __syncthreads();
    }
    if (tid == 0) g_rowptr[n] = carry;
}
__global__ void k_fill(const void* __restrict__ ei, int E) {
    int e = blockIdx.x * blockDim.x + threadIdx.x;
    if (e >= E) return;
    int s = eget(ei, e);
    int d = eget(ei, (long)E + e);
    int pos = atomicAdd(&g_cursor[d], 1);
    g_esrc[pos] = s;
    g_enrm[pos] = g_dinv[s] * g_dinv[d];
}

// ---------------- HMMA helpers ----------------
__device__ __forceinline__ void ldm_x4(uint32_t* r, const void* p) {
    uint32_t a = (uint32_t)__cvta_generic_to_shared(p);
    asm volatile("ldmatrix.sync.aligned.m8n8.x4.shared.b16 {%0,%1,%2,%3}, [%4];"
                 : "=r"(r[0]), "=r"(r[1]), "=r"(r[2]), "=r"(r[3]) : "r"(a));
}
__device__ __forceinline__ void ldm_x4_t(uint32_t* r, const void* p) {
    uint32_t a = (uint32_t)__cvta_generic_to_shared(p);
    asm volatile("ldmatrix.sync.aligned.m8n8.x4.trans.shared.b16 {%0,%1,%2,%3}, [%4];"
                 : "=r"(r[0]), "=r"(r[1]), "=r"(r[2]), "=r"(r[3]) : "r"(a));
}
__device__ __forceinline__ void mma_bf16(float* c, const uint32_t* a, const uint32_t* b) {
    asm volatile(
        "mma.sync.aligned.m16n8k16.row.col.f32.bf16.bf16.f32 "
        "{%0,%1,%2,%3}, {%4,%5,%6,%7}, {%8,%9}, {%0,%1,%2,%3};"
        : "+f"(c[0]), "+f"(c[1]), "+f"(c[2]), "+f"(c[3])
        : "r"(a[0]), "r"(a[1]), "r"(a[2]), "r"(a[3]), "r"(b[0]), "r"(b[1]));
}
__device__ __forceinline__ void split_bf16(float v, unsigned short& h, unsigned short& l) {
    __nv_bfloat16 hb = __float2bfloat16(v);
    __nv_bfloat16 lb = __float2bfloat16(v - __bfloat162float(hb));
    h = __bfloat16_as_ushort(hb);
    l = __bfloat16_as_ushort(lb);
}

// ---------------- HMMA GEMM with fused BN/ReLU on input: xw = act(A) @ W ----
template <int BN_T>
__global__ void __launch_bounds__(256) gemm_mma(
    const float* __restrict__ A, const float* __restrict__ W,
    const float* __restrict__ scale, const float* __restrict__ shift,
    float* __restrict__ xw,
    int M, int K, int Nr)
{
    constexpr int BM = 128, BK = 32;
    constexpr int ASTR = BK + 8;
    constexpr int BSTR = BN_T + 8;
    constexpr int BN_W = BN_T / 2;
    constexpr int NT = BN_W / 8;
    constexpr int NG = BN_W / 16;

    __shared__ __nv_bfloat16 As[2][BM][ASTR];
    __shared__ __nv_bfloat16 Bs[2][BK][BSTR];

    const int tid = threadIdx.x;
    const int wid = tid >> 5, lane = tid & 31;
    const int warp_m = wid >> 1, warp_n = wid & 1;
    const int blockRow = blockIdx.x * BM;
    const int colBase = blockIdx.y * BN_T;

    float acc[2][NT][4];
#pragma unroll
    for (int m = 0; m < 2; m++)
#pragma unroll
        for (int n = 0; n < NT; n++)
#pragma unroll
            for (int j = 0; j < 4; j++) acc[m][n][j] = 0.0f;

    for (int k0 = 0; k0 < K; k0 += BK) {
        __syncthreads();
#pragma unroll
        for (int p = 0; p < 4; p++) {
            int row = (tid >> 3) + p * 32;
            int c4 = (tid & 7) * 4;
            long gr = blockRow + row;
            float v[4] = {0.f, 0.f, 0.f, 0.f};
            if (gr < M) {
                float4 t = *(const float4*)&A[gr * K + k0 + c4];
                v[0] = t.x; v[1] = t.y; v[2] = t.z; v[3] = t.w;
                if (scale) {
#pragma unroll
                    for (int j = 0; j < 4; j++) {
                        int k = k0 + c4 + j;
                        v[j] = fmaxf(0.0f, fmaf(v[j], __ldg(&scale[k]), __ldg(&shift[k])));
                    }
                }
            }
            unsigned short h[4], l[4];
#pragma unroll
            for (int j = 0; j < 4; j++) split_bf16(v[j], h[j], l[j]);
            *(ushort4*)&As[0][row][c4] = make_ushort4(h[0], h[1], h[2], h[3]);
            *(ushort4*)&As[1][row][c4] = make_ushort4(l[0], l[1], l[2], l[3]);
        }
#pragma unroll
        for (int p = 0; p < BN_T / 32; p++) {
            int row = tid >> 3;
            int colt = (tid & 7) * 4 + p * 32;
            int gcol = colBase + colt;
            float v[4] = {0.f, 0.f, 0.f, 0.f};
            if (gcol < Nr) {
                float4 t = *(const float4*)&W[(long)(k0 + row) * Nr + gcol];
                v[0] = t.x; v[1] = t.y; v[2] = t.z; v[3] = t.w;
            }
            unsigned short h[4], l[4];
#pragma unroll
            for (int j = 0; j < 4; j++) split_bf16(v[j], h[j], l[j]);
            *(ushort4*)&Bs[0][row][colt] = make_ushort4(h[0], h[1], h[2], h[3]);
            *(ushort4*)&Bs[1][row][colt] = make_ushort4(l[0], l[1], l[2], l[3]);
        }
        __syncthreads();

#pragma unroll
        for (int ks = 0; ks < 2; ks++) {
            uint32_t ah[2][4], al[2][4];
#pragma unroll
            for (int tm = 0; tm < 2; tm++) {
                int r = warp_m * 32 + tm * 16 + (lane & 15);
                int cc = ks * 16 + (lane >> 4) * 8;
                ldm_x4(ah[tm], &As[0][r][cc]);
                ldm_x4(al[tm], &As[1][r][cc]);
            }
            uint32_t bh[NG][4], bl[NG][4];
#pragma unroll
            for (int ng = 0; ng < NG; ng++) {
                int r = ks * 16 + (lane & 15);
                int cc = warp_n * BN_W + ng * 16 + (lane >> 4) * 8;
                ldm_x4_t(bh[ng], &Bs[0][r][cc]);
                ldm_x4_t(bl[ng], &Bs[1][r][cc]);
            }
#pragma unroll
            for (int tm = 0; tm < 2; tm++)
#pragma unroll
                for (int nn = 0; nn < NT; nn++) {
                    const uint32_t* bH = &bh[nn >> 1][(nn & 1) * 2];
                    const uint32_t* bL = &bl[nn >> 1][(nn & 1) * 2];
                    mma_bf16(acc[tm][nn], ah[tm], bH);
                    mma_bf16(acc[tm][nn], ah[tm], bL);
                    mma_bf16(acc[tm][nn], al[tm], bH);
                }
        }
    }

    const int warpCol = colBase + warp_n * BN_W;
#pragma unroll
    for (int tm = 0; tm < 2; tm++) {
        int r0 = blockRow + warp_m * 32 + tm * 16 + (lane >> 2);
#pragma unroll
        for (int h = 0; h < 2; h++) {
            long row = r0 + h * 8;
            if (row >= M) continue;
#pragma unroll
            for (int nn = 0; nn < NT; nn++) {
                int col = warpCol + nn * 8 + (lane & 3) * 2;
                if (col >= Nr) continue;
                float2 v = make_float2(acc[tm][nn][h * 2], acc[tm][nn][h * 2 + 1]);
                *(float2*)&xw[row * Nr + col] = v;
            }
        }
    }
}

// ---------------- CSR gather aggregation (no atomics) ----------------
// out[i,:] = bias + dinv[i]^2 * xw[i,:] + sum_{e in CSR row i} nrm_e * xw[src_e,:]
__global__ void k_gather256(float* __restrict__ out, const float* __restrict__ xw,
                            const float* __restrict__ bias, int n) {
    int node = (blockIdx.x * blockDim.x + threadIdx.x) >> 5;
    int lane = threadIdx.x & 31;
    if (node >= n) return;
    float dv = g_dinv[node];
    float dv2 = dv * dv;
    const float4* xself = (const float4*)(xw + (long)node * HIDDEN);
    float4 s0 = xself[lane];
    float4 s1 = xself[lane + 32];
    float4 a0 = make_float4(dv2 * s0.x, dv2 * s0.y, dv2 * s0.z, dv2 * s0.w);
    float4 a1 = make_float4(dv2 * s1.x, dv2 * s1.y, dv2 * s1.z, dv2 * s1.w);
    int b = g_rowptr[node], e = g_rowptr[node + 1];
    for (int p = b; p < e; p++) {
        int s = g_esrc[p];
        float nm = g_enrm[p];
        const float4* xs = (const float4*)(xw + (long)s * HIDDEN);
        float4 v0 = __ldg(&xs[lane]);
        float4 v1 = __ldg(&xs[lane + 32]);
        a0.x = fmaf(nm, v0.x, a0.x); a0.y = fmaf(nm, v0.y, a0.y);
        a0.z = fmaf(nm, v0.z, a0.z); a0.w = fmaf(nm, v0.w, a0.w);
        a1.x = fmaf(nm, v1.x, a1.x); a1.y = fmaf(nm, v1.y, a1.y);
        a1.z = fmaf(nm, v1.z, a1.z); a1.w = fmaf(nm, v1.w, a1.w);
    }
    const float4* b4 = (const float4*)bias;
    float4 bb0 = __ldg(&b4[lane]);
    float4 bb1 = __ldg(&b4[lane + 32]);
    a0.x += bb0.x; a0.y += bb0.y; a0.z += bb0.z; a0.w += bb0.w;
    a1.x += bb1.x; a1.y += bb1.y; a1.z += bb1.z; a1.w += bb1.w;
    float4* o = (float4*)(out + (long)node * HIDDEN);
    o[lane] = a0;
    o[lane + 32] = a1;
}

__global__ void k_gather40(float* __restrict__ out, const float* __restrict__ xw,
                           const float* __restrict__ bias, int n) {
    int node = (blockIdx.x * blockDim.x + threadIdx.x) >> 5;
    int lane = threadIdx.x & 31;
    if (node >= n) return;
    float dv = g_dinv[node];
    float dv2 = dv * dv;
    const float* xself = xw + (long)node * N_CLASSES;
    bool hi = (lane + 32 < N_CLASSES);
    float a0 = dv2 * xself[lane];
    float a1 = hi ? dv2 * xself[lane + 32] : 0.0f;
    int b = g_rowptr[node], e = g_rowptr[node + 1];
    for (int p = b; p < e; p++) {
        int s = g_esrc[p];
        float nm = g_enrm[p];
        const float* xs = xw + (long)s * N_CLASSES;
        a0 = fmaf(nm, __ldg(&xs[lane]), a0);
        if (hi) a1 = fmaf(nm, __ldg(&xs[lane + 32]), a1);
    }
    float* o = out + (long)node * N_CLASSES;
    o[lane] = a0 + __ldg(&bias[lane]);
    if (hi) o[lane + 32] = a1 + __ldg(&bias[lane + 32]);
}

// ---------------- batchnorm stats -> scale/shift ----------------
__global__ void k_zero_stats() {
    int c = threadIdx.x;
    g_sum[c] = 0.0f;
    g_sumsq[c] = 0.0f;
}
__global__ void k_bn_stats(const float* __restrict__ h, int n) {
    int c = threadIdx.x;
    int chunk = (n + gridDim.x - 1) / gridDim.x;
    int r0 = blockIdx.x * chunk;
    int r1 = min(n, r0 + chunk);
    float s = 0.0f, ss = 0.0f;
    for (int r = r0; r < r1; r++) {
        float v = h[(long)r * HIDDEN + c];
        s += v;
        ss += v * v;
    }
    atomicAdd(&g_sum[c], s);
    atomicAdd(&g_sumsq[c], ss);
}
__global__ void k_bn_finalize(const float* __restrict__ gamma,
                              const float* __restrict__ beta, int n) {
    int c = threadIdx.x;
    float inv_n = 1.0f / (float)n;
    float mean = g_sum[c] * inv_n;
    float var  = g_sumsq[c] * inv_n - mean * mean;
    float sc = gamma[c] * rsqrtf(var + BN_EPS);
    g_scale[c] = sc;
    g_shift[c] = beta[c] - mean * sc;
}

// ---------------- log_softmax (warp per row) ----------------
__global__ void k_logsoftmax(float* __restrict__ out, int n) {
    int gw   = (blockIdx.x * blockDim.x + threadIdx.x) >> 5;
    int lane = threadIdx.x & 31;
    if (gw >= n) return;
    float* row = out + (long)gw * N_CLASSES;
    float v0 = row[lane];
    float v1 = (lane + 32 < N_CLASSES) ? row[lane + 32] : -1e30f;
    float m = fmaxf(v0, v1);
#pragma unroll
    for (int o = 16; o > 0; o >>= 1)
        m = fmaxf(m, __shfl_xor_sync(0xFFFFFFFFu, m, o));
    float s = expf(v0 - m) + ((lane + 32 < N_CLASSES) ? expf(v1 - m) : 0.0f);
#pragma unroll
    for (int o = 16; o > 0; o >>= 1)
        s += __shfl_xor_sync(0xFFFFFFFFu, s, o);
    float lse = m + logf(s);
    row[lane] = v0 - lse;
    if (lane + 32 < N_CLASSES) row[lane + 32] = v1 - lse;
}

// ---------------- launch ----------------
extern "C" void kernel_launch(void* const* d_in, const int* in_sizes, int n_in,
                              void* d_out, int out_size) {
    const float* x   = (const float*)d_in[0];
    const void*  ei  = d_in[1];
    const float* W1  = (const float*)d_in[2];
    const float* b1  = (const float*)d_in[3];
    const float* g1  = (const float*)d_in[4];
    const float* be1 = (const float*)d_in[5];
    const float* W2  = (const float*)d_in[6];
    const float* b2  = (const float*)d_in[7];
    const float* g2  = (const float*)d_in[8];
    const float* be2 = (const float*)d_in[9];
    const float* W3  = (const float*)d_in[10];
    const float* b3  = (const float*)d_in[11];
    float* out = (float*)d_out;

    const int N = N_NODES;
    const int E = in_sizes[1] / 2;

    float *pA, *pB, *pC, *pScale, *pShift;
    cudaGetSymbolAddress((void**)&pA, g_bufA);
    cudaGetSymbolAddress((void**)&pB, g_bufB);
    cudaGetSymbolAddress((void**)&pC, g_bufC);
    cudaGetSymbolAddress((void**)&pScale, g_scale);
    cudaGetSymbolAddress((void**)&pShift, g_shift);

    // ---- CSR preamble (5 launches; launch #6 = gemm1 for ncu -s 5) ----
    k_detect_zero<<<1, 1024>>>((const int*)ei, N);
    k_hist<<<(E + 255) / 256, 256>>>(ei, E);
    k_dinv<<<(N + 255) / 256, 256>>>(N);
    k_scan<<<1, 1024>>>(N);
    k_fill<<<(E + 255) / 256, 256>>>(ei, E);

    const int mTiles = (N + 127) / 128;
    dim3 gHid(mTiles, 2);
    dim3 gCls(mTiles, 1);
    int gatherBlocks = (N * 32 + 255) / 256;

    // ---- layer 1 ----
    gemm_mma<128><<<gHid, 256>>>(x, W1, nullptr, nullptr, pA, N, IN_FEAT, HIDDEN);
    k_gather256<<<gatherBlocks, 256>>>(pB, pA, b1, N);
    k_zero_stats<<<1, HIDDEN>>>();
    k_bn_stats<<<512, HIDDEN>>>(pB, N);
    k_bn_finalize<<<1, HIDDEN>>>(g1, be1, N);

    // ---- layer 2 ----
    gemm_mma<128><<<gHid, 256>>>(pB, W2, pScale, pShift, pA, N, HIDDEN, HIDDEN);
    k_gather256<<<gatherBlocks, 256>>>(pC, pA, b2, N);
    k_zero_stats<<<1, HIDDEN>>>();
    k_bn_stats<<<512, HIDDEN>>>(pC, N);
    k_bn_finalize<<<1, HIDDEN>>>(g2, be2, N);

    // ---- layer 3 ----
    gemm_mma<64><<<gCls, 256>>>(pC, W3, pScale, pShift, pA, N, HIDDEN, N_CLASSES);
    k_gather40<<<gatherBlocks, 256>>>(out, pA, b3, N);
    k_logsoftmax<<<(N * 32 + 255) / 256, 256>>>(out, N);
}

// round 6
// speedup vs baseline: 2.3125x; 1.1684x over previous
#include <cuda_runtime.h>
#include <cuda_bf16.h>
#include <math.h>
#include <stdint.h>

#define N_NODES   50000
#define IN_FEAT   128
#define HIDDEN    256
#define N_CLASSES 40
#define MAX_E     320000
#define BN_EPS    1e-5f

// ---------------- scratch (device globals; no allocation) ----------------
__device__ float g_bufA[N_NODES * HIDDEN];
__device__ float g_bufB[N_NODES * HIDDEN];
__device__ float g_bufC[N_NODES * HIDDEN];
__device__ float g_dinv[N_NODES];
__device__ int   g_cnt[N_NODES];
__device__ int   g_rowptr[N_NODES + 1];
__device__ int   g_cursor[N_NODES];
__device__ int   g_blksum[64];
__device__ int   g_esrc[MAX_E];
__device__ float g_enrm[MAX_E];
__device__ float g_sum[HIDDEN];
__device__ float g_sumsq[HIDDEN];
__device__ float g_scale[HIDDEN];
__device__ float g_shift[HIDDEN];
__device__ int   g_is64;

// ---------------- dtype probe + zero histogram (grid-wide) ----------------
__global__ void k_detect_zero(const int* __restrict__ ei32, int n) {
    int i = blockIdx.x * blockDim.x + threadIdx.x;
    if (i < n) g_cnt[i] = 0;
    if (blockIdx.x == 0) {
        __shared__ int nz;
        if (threadIdx.x == 0) nz = 0;
        __syncthreads();
        for (int j = threadIdx.x; j < 1024; j += blockDim.x)
            if (ei32[2 * j + 1] != 0) nz = 1;
        __syncthreads();
        if (threadIdx.x == 0) g_is64 = (nz == 0) ? 1 : 0;
    }
}
__device__ __forceinline__ int eget(const void* ei, long pos) {
    if (g_is64) return (int)__ldg(((const long long*)ei) + pos);
    return __ldg(((const int*)ei) + pos);
}

// ---------------- CSR build ----------------
__global__ void k_hist(const void* __restrict__ ei, int E) {
    int e = blockIdx.x * blockDim.x + threadIdx.x;
    if (e >= E) return;
    atomicAdd(&g_cnt[eget(ei, (long)E + e)], 1);
}

// per-1024-block exclusive scan + dinv; block totals to g_blksum
__global__ void __launch_bounds__(1024) k_prep(int n) {
    __shared__ int wsum[32];
    const int t = threadIdx.x, b = blockIdx.x;
    const int lane = t & 31, w = t >> 5;
    int i = (b << 10) + t;
    int v = (i < n) ? g_cnt[i] : 0;
    if (i < n) g_dinv[i] = rsqrtf(1.0f + (float)v);
    int inc = v;
#pragma unroll
    for (int o = 1; o < 32; o <<= 1) {
        int tt = __shfl_up_sync(0xFFFFFFFFu, inc, o);
        if (lane >= o) inc += tt;
    }
    if (lane == 31) wsum[w] = inc;
    __syncthreads();
    if (w == 0) {
        int s = wsum[lane];
#pragma unroll
        for (int o = 1; o < 32; o <<= 1) {
            int tt = __shfl_up_sync(0xFFFFFFFFu, s, o);
            if (lane >= o) s += tt;
        }
        wsum[lane] = s;
    }
    __syncthreads();
    int excl = ((w == 0) ? 0 : wsum[w - 1]) + inc - v;
    if (i < n) g_rowptr[i] = excl;
    if (t == 1023) g_blksum[b] = excl + v;
}

// scan the <=64 block sums (exclusive), write grand total to rowptr[n]
__global__ void k_scanblk(int nb, int n) {
    __shared__ int ws[2];
    const int t = threadIdx.x;       // blockDim = 64
    const int lane = t & 31, w = t >> 5;
    int v = (t < nb) ? g_blksum[t] : 0;
    int inc = v;
#pragma unroll
    for (int o = 1; o < 32; o <<= 1) {
        int tt = __shfl_up_sync(0xFFFFFFFFu, inc, o);
        if (lane >= o) inc += tt;
    }
    if (lane == 31) ws[w] = inc;
    __syncthreads();
    int off = (w == 1) ? ws[0] : 0;
    if (t < nb) g_blksum[t] = off + inc - v;
    if (t == 0) g_rowptr[n] = ws[0] + ws[1];
}

__global__ void k_addoff(int n) {
    int i = blockIdx.x * blockDim.x + threadIdx.x;
    if (i >= n) return;
    int r = g_rowptr[i] + g_blksum[i >> 10];
    g_rowptr[i] = r;
    g_cursor[i] = r;
}

__global__ void k_fill(const void* __restrict__ ei, int E) {
    int e = blockIdx.x * blockDim.x + threadIdx.x;
    if (e >= E) return;
    int s = eget(ei, e);
    int d = eget(ei, (long)E + e);
    int pos = atomicAdd(&g_cursor[d], 1);
    g_esrc[pos] = s;
    g_enrm[pos] = g_dinv[s] * g_dinv[d];
}

// ---------------- HMMA helpers ----------------
__device__ __forceinline__ void ldm_x4(uint32_t* r, const void* p) {
    uint32_t a = (uint32_t)__cvta_generic_to_shared(p);
    asm volatile("ldmatrix.sync.aligned.m8n8.x4.shared.b16 {%0,%1,%2,%3}, [%4];"
                 : "=r"(r[0]), "=r"(r[1]), "=r"(r[2]), "=r"(r[3]) : "r"(a));
}
__device__ __forceinline__ void ldm_x4_t(uint32_t* r, const void* p) {
    uint32_t a = (uint32_t)__cvta_generic_to_shared(p);
    asm volatile("ldmatrix.sync.aligned.m8n8.x4.trans.shared.b16 {%0,%1,%2,%3}, [%4];"
                 : "=r"(r[0]), "=r"(r[1]), "=r"(r[2]), "=r"(r[3]) : "r"(a));
}
__device__ __forceinline__ void mma_bf16(float* c, const uint32_t* a, const uint32_t* b) {
    asm volatile(
        "mma.sync.aligned.m16n8k16.row.col.f32.bf16.bf16.f32 "
        "{%0,%1,%2,%3}, {%4,%5,%6,%7}, {%8,%9}, {%0,%1,%2,%3};"
        : "+f"(c[0]), "+f"(c[1]), "+f"(c[2]), "+f"(c[3])
        : "r"(a[0]), "r"(a[1]), "r"(a[2]), "r"(a[3]), "r"(b[0]), "r"(b[1]));
}
__device__ __forceinline__ void split_bf16(float v, unsigned short& h, unsigned short& l) {
    __nv_bfloat16 hb = __float2bfloat16(v);
    __nv_bfloat16 lb = __float2bfloat16(v - __bfloat162float(hb));
    h = __bfloat16_as_ushort(hb);
    l = __bfloat16_as_ushort(lb);
}

// ---------------- HMMA GEMM: xw = act(A) @ W (+ bias) ----------------
template <int BN_T>
__global__ void __launch_bounds__(256) gemm_mma(
    const float* __restrict__ A, const float* __restrict__ W,
    const float* __restrict__ scale, const float* __restrict__ shift,
    const float* __restrict__ bias,
    float* __restrict__ xw,
    int M, int K, int Nr)
{
    constexpr int BM = 128, BK = 32;
    constexpr int ASTR = BK + 8;
    constexpr int BSTR = BN_T + 8;
    constexpr int BN_W = BN_T / 2;
    constexpr int NT = BN_W / 8;
    constexpr int NG = BN_W / 16;

    __shared__ __nv_bfloat16 As[2][BM][ASTR];
    __shared__ __nv_bfloat16 Bs[2][BK][BSTR];

    const int tid = threadIdx.x;
    const int wid = tid >> 5, lane = tid & 31;
    const int warp_m = wid >> 1, warp_n = wid & 1;
    const int blockRow = blockIdx.x * BM;
    const int colBase = blockIdx.y * BN_T;

    float acc[2][NT][4];
#pragma unroll
    for (int m = 0; m < 2; m++)
#pragma unroll
        for (int n = 0; n < NT; n++)
#pragma unroll
            for (int j = 0; j < 4; j++) acc[m][n][j] = 0.0f;

    for (int k0 = 0; k0 < K; k0 += BK) {
        __syncthreads();
#pragma unroll
        for (int p = 0; p < 4; p++) {
            int row = (tid >> 3) + p * 32;
            int c4 = (tid & 7) * 4;
            long gr = blockRow + row;
            float v[4] = {0.f, 0.f, 0.f, 0.f};
            if (gr < M) {
                float4 t = *(const float4*)&A[gr * K + k0 + c4];
                v[0] = t.x; v[1] = t.y; v[2] = t.z; v[3] = t.w;
                if (scale) {
#pragma unroll
                    for (int j = 0; j < 4; j++) {
                        int k = k0 + c4 + j;
                        v[j] = fmaxf(0.0f, fmaf(v[j], __ldg(&scale[k]), __ldg(&shift[k])));
                    }
                }
            }
            unsigned short h[4], l[4];
#pragma unroll
            for (int j = 0; j < 4; j++) split_bf16(v[j], h[j], l[j]);
            *(ushort4*)&As[0][row][c4] = make_ushort4(h[0], h[1], h[2], h[3]);
            *(ushort4*)&As[1][row][c4] = make_ushort4(l[0], l[1], l[2], l[3]);
        }
#pragma unroll
        for (int p = 0; p < BN_T / 32; p++) {
            int row = tid >> 3;
            int colt = (tid & 7) * 4 + p * 32;
            int gcol = colBase + colt;
            float v[4] = {0.f, 0.f, 0.f, 0.f};
            if (gcol < Nr) {
                float4 t = *(const float4*)&W[(long)(k0 + row) * Nr + gcol];
                v[0] = t.x; v[1] = t.y; v[2] = t.z; v[3] = t.w;
            }
            unsigned short h[4], l[4];
#pragma unroll
            for (int j = 0; j < 4; j++) split_bf16(v[j], h[j], l[j]);
            *(ushort4*)&Bs[0][row][colt] = make_ushort4(h[0], h[1], h[2], h[3]);
            *(ushort4*)&Bs[1][row][colt] = make_ushort4(l[0], l[1], l[2], l[3]);
        }
        __syncthreads();

#pragma unroll
        for (int ks = 0; ks < 2; ks++) {
            uint32_t ah[2][4], al[2][4];
#pragma unroll
            for (int tm = 0; tm < 2; tm++) {
                int r = warp_m * 32 + tm * 16 + (lane & 15);
                int cc = ks * 16 + (lane >> 4) * 8;
                ldm_x4(ah[tm], &As[0][r][cc]);
                ldm_x4(al[tm], &As[1][r][cc]);
            }
            uint32_t bh[NG][4], bl[NG][4];
#pragma unroll
            for (int ng = 0; ng < NG; ng++) {
                int r = ks * 16 + (lane & 15);
                int cc = warp_n * BN_W + ng * 16 + (lane >> 4) * 8;
                ldm_x4_t(bh[ng], &Bs[0][r][cc]);
                ldm_x4_t(bl[ng], &Bs[1][r][cc]);
            }
#pragma unroll
            for (int tm = 0; tm < 2; tm++)
#pragma unroll
                for (int nn = 0; nn < NT; nn++) {
                    const uint32_t* bH = &bh[nn >> 1][(nn & 1) * 2];
                    const uint32_t* bL = &bl[nn >> 1][(nn & 1) * 2];
                    mma_bf16(acc[tm][nn], ah[tm], bH);
                    mma_bf16(acc[tm][nn], ah[tm], bL);
                    mma_bf16(acc[tm][nn], al[tm], bH);
                }
        }
    }

    const int warpCol = colBase + warp_n * BN_W;
#pragma unroll
    for (int tm = 0; tm < 2; tm++) {
        int r0 = blockRow + warp_m * 32 + tm * 16 + (lane >> 2);
#pragma unroll
        for (int h = 0; h < 2; h++) {
            long row = r0 + h * 8;
            if (row >= M) continue;
#pragma unroll
            for (int nn = 0; nn < NT; nn++) {
                int col = warpCol + nn * 8 + (lane & 3) * 2;
                if (col >= Nr) continue;
                float2 v = make_float2(acc[tm][nn][h * 2], acc[tm][nn][h * 2 + 1]);
                if (bias) {
                    v.x += __ldg(&bias[col]);
                    v.y += __ldg(&bias[col + 1]);
                }
                *(float2*)&xw[row * Nr + col] = v;
            }
        }
    }
}

// ---------------- CSR gather aggregation (no atomics) ----------------
// width 128 (layer-1 pre-aggregation of x, no bias)
__global__ void k_gather128(float* __restrict__ out, const float* __restrict__ x, int n) {
    int node = (blockIdx.x * blockDim.x + threadIdx.x) >> 5;
    int lane = threadIdx.x & 31;
    if (node >= n) return;
    float dv = g_dinv[node];
    float dv2 = dv * dv;
    const float4* xs4 = (const float4*)x;
    float4 s = xs4[(long)node * 32 + lane];
    float4 a = make_float4(dv2 * s.x, dv2 * s.y, dv2 * s.z, dv2 * s.w);
    int b = g_rowptr[node], e = g_rowptr[node + 1];
    for (int p = b; p < e; p++) {
        int src = g_esrc[p];
        float nm = g_enrm[p];
        float4 v = __ldg(&xs4[(long)src * 32 + lane]);
        a.x = fmaf(nm, v.x, a.x); a.y = fmaf(nm, v.y, a.y);
        a.z = fmaf(nm, v.z, a.z); a.w = fmaf(nm, v.w, a.w);
    }
    ((float4*)out)[(long)node * 32 + lane] = a;
}

// width 256 (+bias)
__global__ void k_gather256(float* __restrict__ out, const float* __restrict__ xw,
                            const float* __restrict__ bias, int n) {
    int node = (blockIdx.x * blockDim.x + threadIdx.x) >> 5;
    int lane = threadIdx.x & 31;
    if (node >= n) return;
    float dv = g_dinv[node];
    float dv2 = dv * dv;
    const float4* xself = (const float4*)(xw + (long)node * HIDDEN);
    float4 s0 = xself[lane];
    float4 s1 = xself[lane + 32];
    float4 a0 = make_float4(dv2 * s0.x, dv2 * s0.y, dv2 * s0.z, dv2 * s0.w);
    float4 a1 = make_float4(dv2 * s1.x, dv2 * s1.y, dv2 * s1.z, dv2 * s1.w);
    int b = g_rowptr[node], e = g_rowptr[node + 1];
    for (int p = b; p < e; p++) {
        int src = g_esrc[p];
        float nm = g_enrm[p];
        const float4* xs = (const float4*)(xw + (long)src * HIDDEN);
        float4 v0 = __ldg(&xs[lane]);
        float4 v1 = __ldg(&xs[lane + 32]);
        a0.x = fmaf(nm, v0.x, a0.x); a0.y = fmaf(nm, v0.y, a0.y);
        a0.z = fmaf(nm, v0.z, a0.z); a0.w = fmaf(nm, v0.w, a0.w);
        a1.x = fmaf(nm, v1.x, a1.x); a1.y = fmaf(nm, v1.y, a1.y);
        a1.z = fmaf(nm, v1.z, a1.z); a1.w = fmaf(nm, v1.w, a1.w);
    }
    const float4* b4 = (const float4*)bias;
    float4 bb0 = __ldg(&b4[lane]);
    float4 bb1 = __ldg(&b4[lane + 32]);
    a0.x += bb0.x; a0.y += bb0.y; a0.z += bb0.z; a0.w += bb0.w;
    a1.x += bb1.x; a1.y += bb1.y; a1.z += bb1.z; a1.w += bb1.w;
    float4* o = (float4*)(out + (long)node * HIDDEN);
    o[lane] = a0;
    o[lane + 32] = a1;
}

// width 40 (+bias)
__global__ void k_gather40(float* __restrict__ out, const float* __restrict__ xw,
                           const float* __restrict__ bias, int n) {
    int node = (blockIdx.x * blockDim.x + threadIdx.x) >> 5;
    int lane = threadIdx.x & 31;
    if (node >= n) return;
    float dv = g_dinv[node];
    float dv2 = dv * dv;
    const float* xself = xw + (long)node * N_CLASSES;
    bool hi = (lane + 32 < N_CLASSES);
    float a0 = dv2 * xself[lane];
    float a1 = hi ? dv2 * xself[lane + 32] : 0.0f;
    int b = g_rowptr[node], e = g_rowptr[node + 1];
    for (int p = b; p < e; p++) {
        int src = g_esrc[p];
        float nm = g_enrm[p];
        const float* xs = xw + (long)src * N_CLASSES;
        a0 = fmaf(nm, __ldg(&xs[lane]), a0);
        if (hi) a1 = fmaf(nm, __ldg(&xs[lane + 32]), a1);
    }
    float* o = out + (long)node * N_CLASSES;
    o[lane] = a0 + __ldg(&bias[lane]);
    if (hi) o[lane + 32] = a1 + __ldg(&bias[lane + 32]);
}

// ---------------- batchnorm stats -> scale/shift ----------------
__global__ void k_zero_stats() {
    int c = threadIdx.x;
    g_sum[c] = 0.0f;
    g_sumsq[c] = 0.0f;
}
__global__ void k_bn_stats(const float* __restrict__ h, int n) {
    int c = threadIdx.x;
    int chunk = (n + gridDim.x - 1) / gridDim.x;
    int r0 = blockIdx.x * chunk;
    int r1 = min(n, r0 + chunk);
    float s = 0.0f, ss = 0.0f;
    for (int r = r0; r < r1; r++) {
        float v = h[(long)r * HIDDEN + c];
        s += v;
        ss += v * v;
    }
    atomicAdd(&g_sum[c], s);
    atomicAdd(&g_sumsq[c], ss);
}
__global__ void k_bn_finalize(const float* __restrict__ gamma,
                              const float* __restrict__ beta, int n) {
    int c = threadIdx.x;
    float inv_n = 1.0f / (float)n;
    float mean = g_sum[c] * inv_n;
    float var  = g_sumsq[c] * inv_n - mean * mean;
    float sc = gamma[c] * rsqrtf(var + BN_EPS);
    g_scale[c] = sc;
    g_shift[c] = beta[c] - mean * sc;
}

// ---------------- log_softmax (warp per row) ----------------
__global__ void k_logsoftmax(float* __restrict__ out, int n) {
    int gw   = (blockIdx.x * blockDim.x + threadIdx.x) >> 5;
    int lane = threadIdx.x & 31;
    if (gw >= n) return;
    float* row = out + (long)gw * N_CLASSES;
    float v0 = row[lane];
    float v1 = (lane + 32 < N_CLASSES) ? row[lane + 32] : -1e30f;
    float m = fmaxf(v0, v1);
#pragma unroll
    for (int o = 16; o > 0; o >>= 1)
        m = fmaxf(m, __shfl_xor_sync(0xFFFFFFFFu, m, o));
    float s = expf(v0 - m) + ((lane + 32 < N_CLASSES) ? expf(v1 - m) : 0.0f);
#pragma unroll
    for (int o = 16; o > 0; o >>= 1)
        s += __shfl_xor_sync(0xFFFFFFFFu, s, o);
    float lse = m + logf(s);
    row[lane] = v0 - lse;
    if (lane + 32 < N_CLASSES) row[lane + 32] = v1 - lse;
}

// ---------------- launch ----------------
extern "C" void kernel_launch(void* const* d_in, const int* in_sizes, int n_in,
                              void* d_out, int out_size) {
    const float* x   = (const float*)d_in[0];
    const void*  ei  = d_in[1];
    const float* W1  = (const float*)d_in[2];
    const float* b1  = (const float*)d_in[3];
    const float* g1  = (const float*)d_in[4];
    const float* be1 = (const float*)d_in[5];
    const float* W2  = (const float*)d_in[6];
    const float* b2  = (const float*)d_in[7];
    const float* g2  = (const float*)d_in[8];
    const float* be2 = (const float*)d_in[9];
    const float* W3  = (const float*)d_in[10];
    const float* b3  = (const float*)d_in[11];
    float* out = (float*)d_out;

    const int N = N_NODES;
    const int E = in_sizes[1] / 2;
    const int NB = (N + 1023) >> 10;

    float *pA, *pB, *pC, *pScale, *pShift;
    cudaGetSymbolAddress((void**)&pA, g_bufA);
    cudaGetSymbolAddress((void**)&pB, g_bufB);
    cudaGetSymbolAddress((void**)&pC, g_bufC);
    cudaGetSymbolAddress((void**)&pScale, g_scale);
    cudaGetSymbolAddress((void**)&pShift, g_shift);

    // ---- CSR preamble ----
    k_detect_zero<<<(N + 255) / 256, 256>>>((const int*)ei, N);
    k_hist<<<(E + 255) / 256, 256>>>(ei, E);
    k_prep<<<NB, 1024>>>(N);
    k_scanblk<<<1, 64>>>(NB, N);
    k_addoff<<<(N + 255) / 256, 256>>>(N);
    k_fill<<<(E + 255) / 256, 256>>>(ei, E);

    const int mTiles = (N + 127) / 128;
    dim3 gHid(mTiles, 2);
    dim3 gCls(mTiles, 1);
    int gatherBlocks = (N * 32 + 255) / 256;

    // ---- layer 1 (aggregate-first: h1 = (ÂX)W1 + b1) ----
    k_gather128<<<gatherBlocks, 256>>>(pB, x, N);
    gemm_mma<128><<<gHid, 256>>>(pB, W1, nullptr, nullptr, b1, pA, N, IN_FEAT, HIDDEN);
    k_zero_stats<<<1, HIDDEN>>>();
    k_bn_stats<<<512, HIDDEN>>>(pA, N);
    k_bn_finalize<<<1, HIDDEN>>>(g1, be1, N);

    // ---- layer 2 ----
    gemm_mma<128><<<gHid, 256>>>(pA, W2, pScale, pShift, nullptr, pB, N, HIDDEN, HIDDEN);
    k_gather256<<<gatherBlocks, 256>>>(pC, pB, b2, N);
    k_zero_stats<<<1, HIDDEN>>>();
    k_bn_stats<<<512, HIDDEN>>>(pC, N);
    k_bn_finalize<<<1, HIDDEN>>>(g2, be2, N);

    // ---- layer 3 ----
    gemm_mma<64><<<gCls, 256>>>(pC, W3, pScale, pShift, nullptr, pA, N, HIDDEN, N_CLASSES);
    k_gather40<<<gatherBlocks, 256>>>(out, pA, b3, N);
    k_logsoftmax<<<(N * 32 + 255) / 256, 256>>>(out, N);
}